// round 1
// baseline (speedup 1.0000x reference)
#include <cuda_runtime.h>

#define NN 50000
#define EE 800000
#define DD 128
#define LL 5
#define GG 1000

// Scratch (device globals; no allocation allowed)
__device__ float g_z[NN * DD];          // z = h + aggr
__device__ float g_h[2][NN * DD];       // ping-pong hidden states
__device__ float g_sums[GG * DD];       // per-graph sums
__device__ float g_cnt[GG];             // per-graph counts

// ---------------------------------------------------------------------------
// z = h  (initialize aggregation buffer with self term)
// ---------------------------------------------------------------------------
__global__ void zinit_kernel(const float* __restrict__ x, int insel) {
    const float* cur = (insel < 0) ? x : g_h[insel];
    int i = blockIdx.x * blockDim.x + threadIdx.x;   // float4 index, exact grid
    reinterpret_cast<float4*>(g_z)[i] =
        reinterpret_cast<const float4*>(cur)[i];
}

// ---------------------------------------------------------------------------
// z[dst] += h[src] for every edge. Warp per edge, lane owns one float4.
// ---------------------------------------------------------------------------
__global__ void scatter_kernel(const float* __restrict__ x, int insel,
                               const int* __restrict__ ei) {
    const float* cur = (insel < 0) ? x : g_h[insel];
    int t = blockIdx.x * 256 + threadIdx.x;
    int e = t >> 5;
    int lane = t & 31;
    int src = 0, dst = 0;
    if (lane == 0) { src = ei[e]; dst = ei[EE + e]; }
    src = __shfl_sync(0xffffffffu, src, 0);
    dst = __shfl_sync(0xffffffffu, dst, 0);
    float4 v = reinterpret_cast<const float4*>(cur + (size_t)src * DD)[lane];
    float* p = g_z + (size_t)dst * DD + lane * 4;
    asm volatile("red.global.add.v4.f32 [%0], {%1,%2,%3,%4};"
                 :: "l"(p), "f"(v.x), "f"(v.y), "f"(v.z), "f"(v.w)
                 : "memory");
}

// ---------------------------------------------------------------------------
// Fused 2-layer MLP: h_out = relu(relu(z@W1 + b1)@W2 + b2)
// 64 rows per block, 256 threads. f32x2 packed FMA inner loop.
// Thread (tr = tid>>4, tc = tid&15): rows tr*4..tr*4+3, col pairs 2*tc+32*j.
// ---------------------------------------------------------------------------
__global__ __launch_bounds__(256) void mlp_kernel(
    const float* __restrict__ W1, const float* __restrict__ b1,
    const float* __restrict__ W2, const float* __restrict__ b2,
    int outsel) {
    __shared__ float zs[64][16];
    __shared__ __align__(16) float ws[16][128];
    __shared__ __align__(16) float ts[64][128];

    const int tid = threadIdx.x;
    const int tc = tid & 15;
    const int tr = tid >> 4;
    const int row0 = blockIdx.x * 64;

    unsigned long long acc[4][4];
#pragma unroll
    for (int r = 0; r < 4; ++r)
#pragma unroll
        for (int j = 0; j < 4; ++j) acc[r][j] = 0ull;

    // ---------------- GEMM1: t = relu(z @ W1 + b1) ----------------
    for (int kb = 0; kb < 8; ++kb) {
        __syncthreads();
        {   // load z tile [64][16]
            int linear = tid * 4;
            int r = linear >> 4;
            int k0 = linear & 15;
            int grow = row0 + r;
            float4 v = make_float4(0.f, 0.f, 0.f, 0.f);
            if (grow < NN)
                v = *reinterpret_cast<const float4*>(
                        g_z + (size_t)grow * DD + kb * 16 + k0);
            *reinterpret_cast<float4*>(&zs[r][k0]) = v;
        }
#pragma unroll
        for (int i = 0; i < 2; ++i) {   // load W1 tile [16][128]
            int linear = (tid + i * 256) * 4;
            int k = linear >> 7;
            int c = linear & 127;
            *reinterpret_cast<float4*>(&ws[k][c]) =
                *reinterpret_cast<const float4*>(
                    W1 + (size_t)(kb * 16 + k) * DD + c);
        }
        __syncthreads();
#pragma unroll
        for (int k = 0; k < 16; ++k) {
            unsigned long long bj[4];
#pragma unroll
            for (int j = 0; j < 4; ++j)
                bj[j] = *reinterpret_cast<const unsigned long long*>(
                            &ws[k][2 * tc + 32 * j]);
#pragma unroll
            for (int r = 0; r < 4; ++r) {
                float zv = zs[tr * 4 + r][k];
                unsigned long long a;
                asm("mov.b64 %0, {%1, %1};" : "=l"(a) : "f"(zv));
#pragma unroll
                for (int j = 0; j < 4; ++j)
                    asm("fma.rn.f32x2 %0, %1, %2, %0;"
                        : "+l"(acc[r][j]) : "l"(a), "l"(bj[j]));
            }
        }
    }
    // epilogue 1: bias + relu -> ts (smem)
#pragma unroll
    for (int j = 0; j < 4; ++j) {
        int c = 2 * tc + 32 * j;
        float b1a = b1[c], b1b = b1[c + 1];
#pragma unroll
        for (int r = 0; r < 4; ++r) {
            float lo, hi;
            asm("mov.b64 {%0, %1}, %2;" : "=f"(lo), "=f"(hi) : "l"(acc[r][j]));
            ts[tr * 4 + r][c]     = fmaxf(lo + b1a, 0.f);
            ts[tr * 4 + r][c + 1] = fmaxf(hi + b1b, 0.f);
            acc[r][j] = 0ull;
        }
    }

    // ---------------- GEMM2: h = relu(t @ W2 + b2) ----------------
    for (int kb = 0; kb < 8; ++kb) {
        __syncthreads();
#pragma unroll
        for (int i = 0; i < 2; ++i) {   // load W2 tile [16][128]
            int linear = (tid + i * 256) * 4;
            int k = linear >> 7;
            int c = linear & 127;
            *reinterpret_cast<float4*>(&ws[k][c]) =
                *reinterpret_cast<const float4*>(
                    W2 + (size_t)(kb * 16 + k) * DD + c);
        }
        __syncthreads();
#pragma unroll
        for (int k = 0; k < 16; ++k) {
            unsigned long long bj[4];
#pragma unroll
            for (int j = 0; j < 4; ++j)
                bj[j] = *reinterpret_cast<const unsigned long long*>(
                            &ws[k][2 * tc + 32 * j]);
#pragma unroll
            for (int r = 0; r < 4; ++r) {
                float zv = ts[tr * 4 + r][kb * 16 + k];
                unsigned long long a;
                asm("mov.b64 %0, {%1, %1};" : "=l"(a) : "f"(zv));
#pragma unroll
                for (int j = 0; j < 4; ++j)
                    asm("fma.rn.f32x2 %0, %1, %2, %0;"
                        : "+l"(acc[r][j]) : "l"(a), "l"(bj[j]));
            }
        }
    }
    // epilogue 2: bias + relu -> g_h[outsel] (global)
    float* hout = g_h[outsel];
#pragma unroll
    for (int j = 0; j < 4; ++j) {
        int c = 2 * tc + 32 * j;
        float b2a = b2[c], b2b = b2[c + 1];
#pragma unroll
        for (int r = 0; r < 4; ++r) {
            float lo, hi;
            asm("mov.b64 {%0, %1}, %2;" : "=f"(lo), "=f"(hi) : "l"(acc[r][j]));
            float2 o;
            o.x = fmaxf(lo + b2a, 0.f);
            o.y = fmaxf(hi + b2b, 0.f);
            int grow = row0 + tr * 4 + r;
            if (grow < NN)
                *reinterpret_cast<float2*>(hout + (size_t)grow * DD + c) = o;
        }
    }
}

// ---------------------------------------------------------------------------
// Pooling
// ---------------------------------------------------------------------------
__global__ void poolzero_kernel() {
    int i = blockIdx.x * blockDim.x + threadIdx.x;   // 500*256 = 128000 exact
    g_sums[i] = 0.f;
    if (i < GG) g_cnt[i] = 0.f;
}

__global__ void pool_kernel(const int* __restrict__ batch) {
    const float* cur = g_h[(LL - 1) & 1];   // final layer output (g_h[0])
    int t = blockIdx.x * 256 + threadIdx.x;
    int n = t >> 5;
    int lane = t & 31;
    int b = 0;
    if (lane == 0) b = batch[n];
    b = __shfl_sync(0xffffffffu, b, 0);
    float4 v = reinterpret_cast<const float4*>(cur + (size_t)n * DD)[lane];
    float* p = g_sums + (size_t)b * DD + lane * 4;
    asm volatile("red.global.add.v4.f32 [%0], {%1,%2,%3,%4};"
                 :: "l"(p), "f"(v.x), "f"(v.y), "f"(v.z), "f"(v.w)
                 : "memory");
    if (lane == 0) atomicAdd(&g_cnt[b], 1.0f);
}

__global__ void head_kernel(const float* __restrict__ Wh,
                            const float* __restrict__ bh,
                            float* __restrict__ out) {
    int g = blockIdx.x;
    int d = threadIdx.x;   // 128 threads
    float c = fmaxf(g_cnt[g], 1.0f);
    float v = g_sums[(size_t)g * DD + d] / c * Wh[d];
#pragma unroll
    for (int o = 16; o > 0; o >>= 1)
        v += __shfl_down_sync(0xffffffffu, v, o);
    __shared__ float red[4];
    if ((d & 31) == 0) red[d >> 5] = v;
    __syncthreads();
    if (d == 0) out[g] = red[0] + red[1] + red[2] + red[3] + bh[0];
}

// ---------------------------------------------------------------------------
extern "C" void kernel_launch(void* const* d_in, const int* in_sizes, int n_in,
                              void* d_out, int out_size) {
    const float* x    = (const float*)d_in[0];
    const int*   ei   = (const int*)  d_in[1];
    const int*   batch= (const int*)  d_in[2];
    const float* W1s  = (const float*)d_in[3];
    const float* b1s  = (const float*)d_in[4];
    const float* W2s  = (const float*)d_in[5];
    const float* b2s  = (const float*)d_in[6];
    const float* Wh   = (const float*)d_in[7];
    const float* bh   = (const float*)d_in[8];
    float* out = (float*)d_out;

    int insel = -1;
    for (int l = 0; l < LL; ++l) {
        zinit_kernel<<<NN * DD / 4 / 256, 256>>>(x, insel);
        scatter_kernel<<<EE / 8, 256>>>(x, insel, ei);
        mlp_kernel<<<(NN + 63) / 64, 256>>>(
            W1s + (size_t)l * DD * DD, b1s + (size_t)l * DD,
            W2s + (size_t)l * DD * DD, b2s + (size_t)l * DD, l & 1);
        insel = l & 1;
    }
    poolzero_kernel<<<500, 256>>>();
    pool_kernel<<<NN * 32 / 256, 256>>>(batch);
    head_kernel<<<GG, 128>>>(Wh, bh, out);
}

// round 2
// speedup vs baseline: 1.5020x; 1.5020x over previous
#include <cuda_runtime.h>

#define NN 50000
#define EE 800000
#define DD 128
#define LL 5
#define GG 1000

#define SCAN_B 512
#define NB ((NN + SCAN_B - 1) / SCAN_B)   // 98

// Scratch (device globals; no allocation allowed)
__device__ float g_z[NN * DD];          // z = h + aggr
__device__ float g_h[2][NN * DD];       // ping-pong hidden states
__device__ float g_sums[GG * DD];       // per-graph sums
__device__ float g_cnt[GG];             // per-graph counts
// CSR scratch
__device__ int g_deg[NN];
__device__ int g_off[NN];
__device__ int g_cursor[NN];
__device__ int g_adj[EE];
__device__ int g_scan[NB * SCAN_B];
__device__ int g_bsums[NB];
__device__ int g_boff[NB];

// ---------------------------------------------------------------------------
// CSR build: deg histogram -> blocked scan -> bucket fill
// ---------------------------------------------------------------------------
__global__ void deg_zero_kernel() {
    int i = blockIdx.x * blockDim.x + threadIdx.x;
    if (i < NN) { g_deg[i] = 0; g_cursor[i] = 0; }
}

__global__ void deg_count_kernel(const int* __restrict__ ei) {
    int e = blockIdx.x * blockDim.x + threadIdx.x;   // exact grid EE/256
    atomicAdd(&g_deg[ei[EE + e]], 1);
}

__global__ void scan_blocks_kernel() {
    __shared__ int s[SCAN_B];
    int tid = threadIdx.x;
    int i = blockIdx.x * SCAN_B + tid;
    int v = (i < NN) ? g_deg[i] : 0;
    s[tid] = v;
    __syncthreads();
#pragma unroll
    for (int o = 1; o < SCAN_B; o <<= 1) {
        int t = 0;
        if (tid >= o) t = s[tid - o];
        __syncthreads();
        s[tid] += t;
        __syncthreads();
    }
    g_scan[i] = s[tid];
    if (tid == SCAN_B - 1) g_bsums[blockIdx.x] = s[tid];
}

__global__ void scan_top_kernel() {
    __shared__ int s[128];
    int tid = threadIdx.x;   // 128 threads, NB=98 <= 128
    int v = (tid < NB) ? g_bsums[tid] : 0;
    s[tid] = v;
    __syncthreads();
#pragma unroll
    for (int o = 1; o < 128; o <<= 1) {
        int t = 0;
        if (tid >= o) t = s[tid - o];
        __syncthreads();
        s[tid] += t;
        __syncthreads();
    }
    if (tid < NB) g_boff[tid] = s[tid] - v;   // exclusive
}

__global__ void fill_off_kernel() {
    int i = blockIdx.x * blockDim.x + threadIdx.x;
    if (i < NN)
        g_off[i] = g_scan[i] - g_deg[i] + g_boff[i / SCAN_B];
}

__global__ void fill_adj_kernel(const int* __restrict__ ei) {
    int e = blockIdx.x * blockDim.x + threadIdx.x;   // exact grid
    int dst = ei[EE + e];
    int pos = atomicAdd(&g_cursor[dst], 1);
    g_adj[g_off[dst] + pos] = ei[e];   // store src
}

// ---------------------------------------------------------------------------
// Fused z = h + sum_{j in adj(dst)} h[j].  Warp per node, lane owns float4.
// ---------------------------------------------------------------------------
__global__ __launch_bounds__(256) void gather_kernel(const float* __restrict__ x,
                                                     int insel) {
    const float* cur = (insel < 0) ? x : g_h[insel];
    int t = blockIdx.x * 256 + threadIdx.x;
    int node = t >> 5;
    int lane = t & 31;

    int off = 0, deg = 0;
    if (lane == 0) { off = g_off[node]; deg = g_deg[node]; }
    off = __shfl_sync(0xffffffffu, off, 0);
    deg = __shfl_sync(0xffffffffu, deg, 0);

    float4 acc = reinterpret_cast<const float4*>(cur + (size_t)node * DD)[lane];

    for (int j0 = 0; j0 < deg; j0 += 32) {
        int myidx = 0;
        if (j0 + lane < deg) myidx = g_adj[off + j0 + lane];
        int cnt = min(32, deg - j0);
        int tt = 0;
        // unroll by 4 for MLP of loads
        for (; tt + 4 <= cnt; tt += 4) {
            int s0 = __shfl_sync(0xffffffffu, myidx, tt);
            int s1 = __shfl_sync(0xffffffffu, myidx, tt + 1);
            int s2 = __shfl_sync(0xffffffffu, myidx, tt + 2);
            int s3 = __shfl_sync(0xffffffffu, myidx, tt + 3);
            float4 v0 = reinterpret_cast<const float4*>(cur + (size_t)s0 * DD)[lane];
            float4 v1 = reinterpret_cast<const float4*>(cur + (size_t)s1 * DD)[lane];
            float4 v2 = reinterpret_cast<const float4*>(cur + (size_t)s2 * DD)[lane];
            float4 v3 = reinterpret_cast<const float4*>(cur + (size_t)s3 * DD)[lane];
            acc.x += v0.x; acc.y += v0.y; acc.z += v0.z; acc.w += v0.w;
            acc.x += v1.x; acc.y += v1.y; acc.z += v1.z; acc.w += v1.w;
            acc.x += v2.x; acc.y += v2.y; acc.z += v2.z; acc.w += v2.w;
            acc.x += v3.x; acc.y += v3.y; acc.z += v3.z; acc.w += v3.w;
        }
        for (; tt < cnt; ++tt) {
            int s0 = __shfl_sync(0xffffffffu, myidx, tt);
            float4 v0 = reinterpret_cast<const float4*>(cur + (size_t)s0 * DD)[lane];
            acc.x += v0.x; acc.y += v0.y; acc.z += v0.z; acc.w += v0.w;
        }
    }
    reinterpret_cast<float4*>(g_z + (size_t)node * DD)[lane] = acc;
}

// ---------------------------------------------------------------------------
// Fused 2-layer MLP: h_out = relu(relu(z@W1 + b1)@W2 + b2)
// ---------------------------------------------------------------------------
__global__ __launch_bounds__(256) void mlp_kernel(
    const float* __restrict__ W1, const float* __restrict__ b1,
    const float* __restrict__ W2, const float* __restrict__ b2,
    int outsel) {
    __shared__ float zs[64][16];
    __shared__ __align__(16) float ws[16][128];
    __shared__ __align__(16) float ts[64][128];

    const int tid = threadIdx.x;
    const int tc = tid & 15;
    const int tr = tid >> 4;
    const int row0 = blockIdx.x * 64;

    unsigned long long acc[4][4];
#pragma unroll
    for (int r = 0; r < 4; ++r)
#pragma unroll
        for (int j = 0; j < 4; ++j) acc[r][j] = 0ull;

    // ---------------- GEMM1: t = relu(z @ W1 + b1) ----------------
    for (int kb = 0; kb < 8; ++kb) {
        __syncthreads();
        {   // load z tile [64][16]
            int linear = tid * 4;
            int r = linear >> 4;
            int k0 = linear & 15;
            int grow = row0 + r;
            float4 v = make_float4(0.f, 0.f, 0.f, 0.f);
            if (grow < NN)
                v = *reinterpret_cast<const float4*>(
                        g_z + (size_t)grow * DD + kb * 16 + k0);
            *reinterpret_cast<float4*>(&zs[r][k0]) = v;
        }
#pragma unroll
        for (int i = 0; i < 2; ++i) {   // load W1 tile [16][128]
            int linear = (tid + i * 256) * 4;
            int k = linear >> 7;
            int c = linear & 127;
            *reinterpret_cast<float4*>(&ws[k][c]) =
                *reinterpret_cast<const float4*>(
                    W1 + (size_t)(kb * 16 + k) * DD + c);
        }
        __syncthreads();
#pragma unroll
        for (int k = 0; k < 16; ++k) {
            unsigned long long bj[4];
#pragma unroll
            for (int j = 0; j < 4; ++j)
                bj[j] = *reinterpret_cast<const unsigned long long*>(
                            &ws[k][2 * tc + 32 * j]);
#pragma unroll
            for (int r = 0; r < 4; ++r) {
                float zv = zs[tr * 4 + r][k];
                unsigned long long a;
                asm("mov.b64 %0, {%1, %1};" : "=l"(a) : "f"(zv));
#pragma unroll
                for (int j = 0; j < 4; ++j)
                    asm("fma.rn.f32x2 %0, %1, %2, %0;"
                        : "+l"(acc[r][j]) : "l"(a), "l"(bj[j]));
            }
        }
    }
    // epilogue 1: bias + relu -> ts (smem)
#pragma unroll
    for (int j = 0; j < 4; ++j) {
        int c = 2 * tc + 32 * j;
        float b1a = b1[c], b1b = b1[c + 1];
#pragma unroll
        for (int r = 0; r < 4; ++r) {
            float lo, hi;
            asm("mov.b64 {%0, %1}, %2;" : "=f"(lo), "=f"(hi) : "l"(acc[r][j]));
            ts[tr * 4 + r][c]     = fmaxf(lo + b1a, 0.f);
            ts[tr * 4 + r][c + 1] = fmaxf(hi + b1b, 0.f);
            acc[r][j] = 0ull;
        }
    }

    // ---------------- GEMM2: h = relu(t @ W2 + b2) ----------------
    for (int kb = 0; kb < 8; ++kb) {
        __syncthreads();
#pragma unroll
        for (int i = 0; i < 2; ++i) {   // load W2 tile [16][128]
            int linear = (tid + i * 256) * 4;
            int k = linear >> 7;
            int c = linear & 127;
            *reinterpret_cast<float4*>(&ws[k][c]) =
                *reinterpret_cast<const float4*>(
                    W2 + (size_t)(kb * 16 + k) * DD + c);
        }
        __syncthreads();
#pragma unroll
        for (int k = 0; k < 16; ++k) {
            unsigned long long bj[4];
#pragma unroll
            for (int j = 0; j < 4; ++j)
                bj[j] = *reinterpret_cast<const unsigned long long*>(
                            &ws[k][2 * tc + 32 * j]);
#pragma unroll
            for (int r = 0; r < 4; ++r) {
                float zv = ts[tr * 4 + r][kb * 16 + k];
                unsigned long long a;
                asm("mov.b64 %0, {%1, %1};" : "=l"(a) : "f"(zv));
#pragma unroll
                for (int j = 0; j < 4; ++j)
                    asm("fma.rn.f32x2 %0, %1, %2, %0;"
                        : "+l"(acc[r][j]) : "l"(a), "l"(bj[j]));
            }
        }
    }
    // epilogue 2: bias + relu -> g_h[outsel] (global)
    float* hout = g_h[outsel];
#pragma unroll
    for (int j = 0; j < 4; ++j) {
        int c = 2 * tc + 32 * j;
        float b2a = b2[c], b2b = b2[c + 1];
#pragma unroll
        for (int r = 0; r < 4; ++r) {
            float lo, hi;
            asm("mov.b64 {%0, %1}, %2;" : "=f"(lo), "=f"(hi) : "l"(acc[r][j]));
            float2 o;
            o.x = fmaxf(lo + b2a, 0.f);
            o.y = fmaxf(hi + b2b, 0.f);
            int grow = row0 + tr * 4 + r;
            if (grow < NN)
                *reinterpret_cast<float2*>(hout + (size_t)grow * DD + c) = o;
        }
    }
}

// ---------------------------------------------------------------------------
// Pooling
// ---------------------------------------------------------------------------
__global__ void poolzero_kernel() {
    int i = blockIdx.x * blockDim.x + threadIdx.x;   // 500*256 = 128000 exact
    g_sums[i] = 0.f;
    if (i < GG) g_cnt[i] = 0.f;
}

__global__ void pool_kernel(const int* __restrict__ batch) {
    const float* cur = g_h[(LL - 1) & 1];   // final layer output (g_h[0])
    int t = blockIdx.x * 256 + threadIdx.x;
    int n = t >> 5;
    int lane = t & 31;
    int b = 0;
    if (lane == 0) b = batch[n];
    b = __shfl_sync(0xffffffffu, b, 0);
    float4 v = reinterpret_cast<const float4*>(cur + (size_t)n * DD)[lane];
    float* p = g_sums + (size_t)b * DD + lane * 4;
    asm volatile("red.global.add.v4.f32 [%0], {%1,%2,%3,%4};"
                 :: "l"(p), "f"(v.x), "f"(v.y), "f"(v.z), "f"(v.w)
                 : "memory");
    if (lane == 0) atomicAdd(&g_cnt[b], 1.0f);
}

__global__ void head_kernel(const float* __restrict__ Wh,
                            const float* __restrict__ bh,
                            float* __restrict__ out) {
    int g = blockIdx.x;
    int d = threadIdx.x;   // 128 threads
    float c = fmaxf(g_cnt[g], 1.0f);
    float v = g_sums[(size_t)g * DD + d] / c * Wh[d];
#pragma unroll
    for (int o = 16; o > 0; o >>= 1)
        v += __shfl_down_sync(0xffffffffu, v, o);
    __shared__ float red[4];
    if ((d & 31) == 0) red[d >> 5] = v;
    __syncthreads();
    if (d == 0) out[g] = red[0] + red[1] + red[2] + red[3] + bh[0];
}

// ---------------------------------------------------------------------------
extern "C" void kernel_launch(void* const* d_in, const int* in_sizes, int n_in,
                              void* d_out, int out_size) {
    const float* x    = (const float*)d_in[0];
    const int*   ei   = (const int*)  d_in[1];
    const int*   batch= (const int*)  d_in[2];
    const float* W1s  = (const float*)d_in[3];
    const float* b1s  = (const float*)d_in[4];
    const float* W2s  = (const float*)d_in[5];
    const float* b2s  = (const float*)d_in[6];
    const float* Wh   = (const float*)d_in[7];
    const float* bh   = (const float*)d_in[8];
    float* out = (float*)d_out;

    // --- CSR build (once per launch) ---
    deg_zero_kernel<<<(NN + 255) / 256, 256>>>();
    deg_count_kernel<<<EE / 256, 256>>>(ei);
    scan_blocks_kernel<<<NB, SCAN_B>>>();
    scan_top_kernel<<<1, 128>>>();
    fill_off_kernel<<<(NN + 255) / 256, 256>>>();
    fill_adj_kernel<<<EE / 256, 256>>>(ei);

    int insel = -1;
    for (int l = 0; l < LL; ++l) {
        gather_kernel<<<NN * 32 / 256, 256>>>(x, insel);
        mlp_kernel<<<(NN + 63) / 64, 256>>>(
            W1s + (size_t)l * DD * DD, b1s + (size_t)l * DD,
            W2s + (size_t)l * DD * DD, b2s + (size_t)l * DD, l & 1);
        insel = l & 1;
    }
    poolzero_kernel<<<500, 256>>>();
    pool_kernel<<<NN * 32 / 256, 256>>>(batch);
    head_kernel<<<GG, 128>>>(Wh, bh, out);
}

// round 7
// speedup vs baseline: 1.5516x; 1.0330x over previous
#include <cuda_runtime.h>
#include <cuda_bf16.h>
#include <mma.h>
#include <cstdint>

using namespace nvcuda;

#define NN 50000
#define EE 800000
#define DD 128
#define LL 5
#define GG 1000

#define SCAN_B 512
#define NB ((NN + SCAN_B - 1) / SCAN_B)   // 98

// ---------------------------------------------------------------------------
// Device global scratch (no allocation allowed)
// ---------------------------------------------------------------------------
__device__ float g_z[NN * DD];
__device__ float g_h[2][NN * DD];
__device__ float g_sums[GG * DD];
__device__ float g_cnt[GG];
__device__ int g_deg[NN];
__device__ int g_off[NN];
__device__ int g_cursor[NN];
__device__ int g_adj[EE];
__device__ int g_scan[NB * SCAN_B];
__device__ int g_bsums[NB];
__device__ int g_boff[NB];
// Pre-split weight images [mat(0=W1,1=W2)][layer][k*128+n]
__device__ __nv_bfloat16 g_wh[2][LL][DD * DD];   // hi part
__device__ __nv_bfloat16 g_wl[2][LL][DD * DD];   // lo part

// ---------------------------------------------------------------------------
// CSR build
// ---------------------------------------------------------------------------
__global__ void deg_zero_kernel() {
    int i = blockIdx.x * blockDim.x + threadIdx.x;
    if (i < NN) { g_deg[i] = 0; g_cursor[i] = 0; }
}
__global__ void deg_count_kernel(const int* __restrict__ ei) {
    int e = blockIdx.x * blockDim.x + threadIdx.x;   // exact grid
    atomicAdd(&g_deg[ei[EE + e]], 1);
}
__global__ void scan_blocks_kernel() {
    __shared__ int s[SCAN_B];
    int tid = threadIdx.x;
    int i = blockIdx.x * SCAN_B + tid;
    int v = (i < NN) ? g_deg[i] : 0;
    s[tid] = v;
    __syncthreads();
#pragma unroll
    for (int o = 1; o < SCAN_B; o <<= 1) {
        int t = 0;
        if (tid >= o) t = s[tid - o];
        __syncthreads();
        s[tid] += t;
        __syncthreads();
    }
    g_scan[i] = s[tid];
    if (tid == SCAN_B - 1) g_bsums[blockIdx.x] = s[tid];
}
__global__ void scan_top_kernel() {
    __shared__ int s[128];
    int tid = threadIdx.x;
    int v = (tid < NB) ? g_bsums[tid] : 0;
    s[tid] = v;
    __syncthreads();
#pragma unroll
    for (int o = 1; o < 128; o <<= 1) {
        int t = 0;
        if (tid >= o) t = s[tid - o];
        __syncthreads();
        s[tid] += t;
        __syncthreads();
    }
    if (tid < NB) g_boff[tid] = s[tid] - v;
}
__global__ void fill_off_kernel() {
    int i = blockIdx.x * blockDim.x + threadIdx.x;
    if (i < NN) g_off[i] = g_scan[i] - g_deg[i] + g_boff[i / SCAN_B];
}
__global__ void fill_adj_kernel(const int* __restrict__ ei) {
    int e = blockIdx.x * blockDim.x + threadIdx.x;
    int dst = ei[EE + e];
    int pos = atomicAdd(&g_cursor[dst], 1);
    g_adj[g_off[dst] + pos] = ei[e];
}

// ---------------------------------------------------------------------------
// Weight pre-split: hi = bf16(w), lo = bf16(w - float(hi)), plain [k][n]
// ---------------------------------------------------------------------------
__global__ void prep_w_kernel(const float* __restrict__ W1s,
                              const float* __restrict__ W2s) {
    int idx = blockIdx.x * 256 + threadIdx.x;   // 640*256 = 163840 exact
    int l = idx / 32768;
    int rem = idx & 32767;
    int mat = rem >> 14;
    int e = rem & 16383;
    const float* W = mat ? W2s : W1s;
    float w = W[(size_t)l * 16384 + e];
    __nv_bfloat16 hi = __float2bfloat16(w);
    float lo = w - __bfloat162float(hi);
    g_wh[mat][l][e] = hi;
    g_wl[mat][l][e] = __float2bfloat16(lo);
}

// ---------------------------------------------------------------------------
// Gather: z = h + sum_{j in adj(node)} h[j]
// ---------------------------------------------------------------------------
__global__ __launch_bounds__(256) void gather_kernel(const float* __restrict__ x,
                                                     int insel) {
    const float* cur = (insel < 0) ? x : g_h[insel];
    int t = blockIdx.x * 256 + threadIdx.x;
    int node = t >> 5;
    int lane = t & 31;
    int off = 0, deg = 0;
    if (lane == 0) { off = g_off[node]; deg = g_deg[node]; }
    off = __shfl_sync(0xffffffffu, off, 0);
    deg = __shfl_sync(0xffffffffu, deg, 0);
    float4 acc = reinterpret_cast<const float4*>(cur + (size_t)node * DD)[lane];
    for (int j0 = 0; j0 < deg; j0 += 32) {
        int myidx = 0;
        if (j0 + lane < deg) myidx = g_adj[off + j0 + lane];
        int cnt = min(32, deg - j0);
        int tt = 0;
        for (; tt + 4 <= cnt; tt += 4) {
            int s0 = __shfl_sync(0xffffffffu, myidx, tt);
            int s1 = __shfl_sync(0xffffffffu, myidx, tt + 1);
            int s2 = __shfl_sync(0xffffffffu, myidx, tt + 2);
            int s3 = __shfl_sync(0xffffffffu, myidx, tt + 3);
            float4 v0 = reinterpret_cast<const float4*>(cur + (size_t)s0 * DD)[lane];
            float4 v1 = reinterpret_cast<const float4*>(cur + (size_t)s1 * DD)[lane];
            float4 v2 = reinterpret_cast<const float4*>(cur + (size_t)s2 * DD)[lane];
            float4 v3 = reinterpret_cast<const float4*>(cur + (size_t)s3 * DD)[lane];
            acc.x += v0.x; acc.y += v0.y; acc.z += v0.z; acc.w += v0.w;
            acc.x += v1.x; acc.y += v1.y; acc.z += v1.z; acc.w += v1.w;
            acc.x += v2.x; acc.y += v2.y; acc.z += v2.z; acc.w += v2.w;
            acc.x += v3.x; acc.y += v3.y; acc.z += v3.z; acc.w += v3.w;
        }
        for (; tt < cnt; ++tt) {
            int s0 = __shfl_sync(0xffffffffu, myidx, tt);
            float4 v0 = reinterpret_cast<const float4*>(cur + (size_t)s0 * DD)[lane];
            acc.x += v0.x; acc.y += v0.y; acc.z += v0.z; acc.w += v0.w;
        }
    }
    reinterpret_cast<float4*>(g_z + (size_t)node * DD)[lane] = acc;
}

// ---------------------------------------------------------------------------
// wmma bf16 3-split fused 2-layer MLP. 128 rows/CTA, 256 threads (8 warps),
// warp w owns rows w*16..w*16+15.
// SMEM (bytes): Ah 0, Al 34816, Bh 69632, Bl 104448, STAGE 139264, BIAS 151552
// padded leading dim 136 bf16 (272B) -> conflict-free ldmatrix.
// ---------------------------------------------------------------------------
#define LDA 136
#define A_HI_OFF 0
#define A_LO_OFF 34816
#define B_HI_OFF 69632
#define B_LO_OFF 104448
#define STG_OFF  139264
#define BIAS_OFF 151552
#define MLP_SMEM (BIAS_OFF + 256 * 4)

__device__ __forceinline__ void copy_w_to_smem(__nv_bfloat16* dst,
                                               const __nv_bfloat16* src,
                                               int tid) {
#pragma unroll
    for (int it = 0; it < 8; ++it) {
        int idx = it * 256 + tid;       // 2048 uint4 total
        int k = idx >> 4;               // row
        int q = idx & 15;               // 16B chunk within row
        *reinterpret_cast<uint4*>(
            reinterpret_cast<char*>(dst) + (size_t)k * (LDA * 2) + q * 16) =
            reinterpret_cast<const uint4*>(src + (size_t)k * DD)[q];
    }
}

__global__ __launch_bounds__(256) void mlp_wmma_kernel(
    int l, int outsel,
    const float* __restrict__ b1s, const float* __restrict__ b2s) {
    extern __shared__ char sm[];
    __nv_bfloat16* Ah = reinterpret_cast<__nv_bfloat16*>(sm + A_HI_OFF);
    __nv_bfloat16* Al = reinterpret_cast<__nv_bfloat16*>(sm + A_LO_OFF);
    __nv_bfloat16* Bh = reinterpret_cast<__nv_bfloat16*>(sm + B_HI_OFF);
    __nv_bfloat16* Bl = reinterpret_cast<__nv_bfloat16*>(sm + B_LO_OFF);
    float* bias = reinterpret_cast<float*>(sm + BIAS_OFF);

    const int tid = threadIdx.x;
    const int wid = tid >> 5;
    const int lane = tid & 31;
    const int row0 = blockIdx.x * 128;
    float* stage = reinterpret_cast<float*>(sm + STG_OFF) + wid * 16 * 24;

    // biases -> smem
    if (tid < 128) bias[tid] = b1s[(size_t)l * DD + tid];
    else bias[tid] = b2s[(size_t)l * DD + (tid - 128)];

    // W1 -> Bs
    copy_w_to_smem(Bh, g_wh[0][l], tid);
    copy_w_to_smem(Bl, g_wl[0][l], tid);

    // z rows -> split into Ah/Al
#pragma unroll
    for (int it = 0; it < 16; ++it) {
        int i = it * 256 + tid;          // 4096 float4s
        int r = i >> 5, c4 = i & 31;
        int grow = row0 + r;
        float4 v = make_float4(0.f, 0.f, 0.f, 0.f);
        if (grow < NN)
            v = *reinterpret_cast<const float4*>(g_z + (size_t)grow * DD + c4 * 4);
        __nv_bfloat16 hx = __float2bfloat16(v.x), hy = __float2bfloat16(v.y);
        __nv_bfloat16 hz = __float2bfloat16(v.z), hw = __float2bfloat16(v.w);
        __nv_bfloat162 ph0(hx, hy), ph1(hz, hw);
        __nv_bfloat162 pl0(__float2bfloat16(v.x - __bfloat162float(hx)),
                           __float2bfloat16(v.y - __bfloat162float(hy)));
        __nv_bfloat162 pl1(__float2bfloat16(v.z - __bfloat162float(hz)),
                           __float2bfloat16(v.w - __bfloat162float(hw)));
        uint2 hi, lo;
        hi.x = *reinterpret_cast<uint32_t*>(&ph0);
        hi.y = *reinterpret_cast<uint32_t*>(&ph1);
        lo.x = *reinterpret_cast<uint32_t*>(&pl0);
        lo.y = *reinterpret_cast<uint32_t*>(&pl1);
        size_t boff = (size_t)r * (LDA * 2) + c4 * 8;
        *reinterpret_cast<uint2*>(reinterpret_cast<char*>(Ah) + boff) = hi;
        *reinterpret_cast<uint2*>(reinterpret_cast<char*>(Al) + boff) = lo;
    }
    __syncthreads();

    wmma::fragment<wmma::matrix_a, 16, 16, 16, __nv_bfloat16, wmma::row_major> af;
    wmma::fragment<wmma::matrix_b, 16, 16, 16, __nv_bfloat16, wmma::row_major> bf;
    wmma::fragment<wmma::accumulator, 16, 16, 16, float> cf[8];

    // ---------------- GEMM1 ----------------
#pragma unroll
    for (int nt = 0; nt < 8; ++nt) wmma::fill_fragment(cf[nt], 0.f);
    {
        const __nv_bfloat16* Ab[3] = {Ah, Ah, Al};
        const __nv_bfloat16* Bb[3] = {Bh, Bl, Bh};
#pragma unroll
        for (int p = 0; p < 3; ++p)
#pragma unroll
            for (int k = 0; k < 8; ++k) {
                wmma::load_matrix_sync(af, Ab[p] + (wid * 16) * LDA + k * 16, LDA);
#pragma unroll
                for (int nt = 0; nt < 8; ++nt) {
                    wmma::load_matrix_sync(bf, Bb[p] + (k * 16) * LDA + nt * 16, LDA);
                    wmma::mma_sync(cf[nt], af, bf, cf[nt]);
                }
            }
    }
    // epilogue1: t = relu(D1 + b1), re-split into own A rows (warp-private rows)
#pragma unroll
    for (int nt = 0; nt < 8; ++nt) {
        wmma::store_matrix_sync(stage, cf[nt], 24, wmma::mem_row_major);
        __syncwarp();
        int r = lane >> 1;
        int cb = (lane & 1) * 8;
#pragma unroll
        for (int e = 0; e < 8; ++e) {
            int c = cb + e;
            float t = fmaxf(stage[r * 24 + c] + bias[nt * 16 + c], 0.f);
            __nv_bfloat16 hi = __float2bfloat16(t);
            int pos = (wid * 16 + r) * LDA + nt * 16 + c;
            Ah[pos] = hi;
            Al[pos] = __float2bfloat16(t - __bfloat162float(hi));
        }
        __syncwarp();
    }
    __syncthreads();

    // W2 -> Bs
    copy_w_to_smem(Bh, g_wh[1][l], tid);
    copy_w_to_smem(Bl, g_wl[1][l], tid);
    __syncthreads();

    // ---------------- GEMM2 ----------------
#pragma unroll
    for (int nt = 0; nt < 8; ++nt) wmma::fill_fragment(cf[nt], 0.f);
    {
        const __nv_bfloat16* Ab[3] = {Ah, Ah, Al};
        const __nv_bfloat16* Bb[3] = {Bh, Bl, Bh};
#pragma unroll
        for (int p = 0; p < 3; ++p)
#pragma unroll
            for (int k = 0; k < 8; ++k) {
                wmma::load_matrix_sync(af, Ab[p] + (wid * 16) * LDA + k * 16, LDA);
#pragma unroll
                for (int nt = 0; nt < 8; ++nt) {
                    wmma::load_matrix_sync(bf, Bb[p] + (k * 16) * LDA + nt * 16, LDA);
                    wmma::mma_sync(cf[nt], af, bf, cf[nt]);
                }
            }
    }
    // epilogue2: h = relu(D2 + b2) -> global
    float* hout = g_h[outsel];
#pragma unroll
    for (int nt = 0; nt < 8; ++nt) {
        wmma::store_matrix_sync(stage, cf[nt], 24, wmma::mem_row_major);
        __syncwarp();
        int r = lane >> 1;
        int cb = (lane & 1) * 8;
        int grow = row0 + wid * 16 + r;
        if (grow < NN) {
            float4 o0, o1;
            const float* bb = bias + 128 + nt * 16 + cb;
            const float* ss = stage + r * 24 + cb;
            o0.x = fmaxf(ss[0] + bb[0], 0.f);
            o0.y = fmaxf(ss[1] + bb[1], 0.f);
            o0.z = fmaxf(ss[2] + bb[2], 0.f);
            o0.w = fmaxf(ss[3] + bb[3], 0.f);
            o1.x = fmaxf(ss[4] + bb[4], 0.f);
            o1.y = fmaxf(ss[5] + bb[5], 0.f);
            o1.z = fmaxf(ss[6] + bb[6], 0.f);
            o1.w = fmaxf(ss[7] + bb[7], 0.f);
            float* dst = hout + (size_t)grow * DD + nt * 16 + cb;
            *reinterpret_cast<float4*>(dst) = o0;
            *reinterpret_cast<float4*>(dst + 4) = o1;
        }
        __syncwarp();
    }
}

// ---------------------------------------------------------------------------
// Pooling + head
// ---------------------------------------------------------------------------
__global__ void poolzero_kernel() {
    int i = blockIdx.x * blockDim.x + threadIdx.x;
    g_sums[i] = 0.f;
    if (i < GG) g_cnt[i] = 0.f;
}
__global__ void pool_kernel(const int* __restrict__ batch) {
    const float* cur = g_h[(LL - 1) & 1];
    int t = blockIdx.x * 256 + threadIdx.x;
    int n = t >> 5;
    int lane = t & 31;
    int b = 0;
    if (lane == 0) b = batch[n];
    b = __shfl_sync(0xffffffffu, b, 0);
    float4 v = reinterpret_cast<const float4*>(cur + (size_t)n * DD)[lane];
    float* p = g_sums + (size_t)b * DD + lane * 4;
    asm volatile("red.global.add.v4.f32 [%0], {%1,%2,%3,%4};"
                 :: "l"(p), "f"(v.x), "f"(v.y), "f"(v.z), "f"(v.w) : "memory");
    if (lane == 0) atomicAdd(&g_cnt[b], 1.0f);
}
__global__ void head_kernel(const float* __restrict__ Wh,
                            const float* __restrict__ bh,
                            float* __restrict__ out) {
    int g = blockIdx.x;
    int d = threadIdx.x;
    float c = fmaxf(g_cnt[g], 1.0f);
    float v = g_sums[(size_t)g * DD + d] / c * Wh[d];
#pragma unroll
    for (int o = 16; o > 0; o >>= 1)
        v += __shfl_down_sync(0xffffffffu, v, o);
    __shared__ float red[4];
    if ((d & 31) == 0) red[d >> 5] = v;
    __syncthreads();
    if (d == 0) out[g] = red[0] + red[1] + red[2] + red[3] + bh[0];
}

// ---------------------------------------------------------------------------
extern "C" void kernel_launch(void* const* d_in, const int* in_sizes, int n_in,
                              void* d_out, int out_size) {
    const float* x    = (const float*)d_in[0];
    const int*   ei   = (const int*)  d_in[1];
    const int*   batch= (const int*)  d_in[2];
    const float* W1s  = (const float*)d_in[3];
    const float* b1s  = (const float*)d_in[4];
    const float* W2s  = (const float*)d_in[5];
    const float* b2s  = (const float*)d_in[6];
    const float* Wh   = (const float*)d_in[7];
    const float* bh   = (const float*)d_in[8];
    float* out = (float*)d_out;

    static bool attr_done = false;
    if (!attr_done) {
        cudaFuncSetAttribute(mlp_wmma_kernel,
                             cudaFuncAttributeMaxDynamicSharedMemorySize,
                             MLP_SMEM);
        attr_done = true;
    }

    prep_w_kernel<<<640, 256>>>(W1s, W2s);

    deg_zero_kernel<<<(NN + 255) / 256, 256>>>();
    deg_count_kernel<<<EE / 256, 256>>>(ei);
    scan_blocks_kernel<<<NB, SCAN_B>>>();
    scan_top_kernel<<<1, 128>>>();
    fill_off_kernel<<<(NN + 255) / 256, 256>>>();
    fill_adj_kernel<<<EE / 256, 256>>>(ei);

    int insel = -1;
    for (int l = 0; l < LL; ++l) {
        gather_kernel<<<NN * 32 / 256, 256>>>(x, insel);
        mlp_wmma_kernel<<<(NN + 127) / 128, 256, MLP_SMEM>>>(l, l & 1, b1s, b2s);
        insel = l & 1;
    }
    poolzero_kernel<<<500, 256>>>();
    pool_kernel<<<NN * 32 / 256, 256>>>(batch);
    head_kernel<<<GG, 128>>>(Wh, bh, out);
}

// round 8
// speedup vs baseline: 1.7532x; 1.1299x over previous
#include <cuda_runtime.h>
#include <cuda_bf16.h>
#include <mma.h>
#include <cstdint>

using namespace nvcuda;

#define NN 50000
#define EE 800000
#define DD 128
#define LL 5
#define GG 1000

// ---------------------------------------------------------------------------
// Device global scratch (no allocation allowed)
// ---------------------------------------------------------------------------
__device__ float g_z[NN * DD];
__device__ float g_h[2][NN * DD];
__device__ float g_sums[GG * DD];
__device__ float g_cnt[GG];
__device__ int g_deg[NN];      // zeroed at end of each launch (cleanup_kernel)
__device__ int g_off[NN];
__device__ int g_cursor[NN];   // zeroed at end of each launch
__device__ int g_adj[EE];
// Pre-split weight images [mat(0=W1,1=W2)][layer][k*128+n]
__device__ __nv_bfloat16 g_wh[2][LL][DD * DD];
__device__ __nv_bfloat16 g_wl[2][LL][DD * DD];

// ---------------------------------------------------------------------------
// CSR build.  g_deg / g_cursor are zero on entry (static init on first call,
// cleanup_kernel restores the invariant for every subsequent graph replay).
// ---------------------------------------------------------------------------
__global__ void deg_count_kernel(const int* __restrict__ ei) {
    int e = blockIdx.x * blockDim.x + threadIdx.x;   // exact grid EE/256
    atomicAdd(&g_deg[ei[EE + e]], 1);
}

// Single-block exclusive scan of g_deg -> g_off (1024 threads, 32 warps).
__global__ __launch_bounds__(1024) void scan_all_kernel() {
    __shared__ int warpsums[32];
    const int tid = threadIdx.x;
    const int wid = tid >> 5;
    const int lane = tid & 31;
    int run = 0;
    const int NCHUNK = (NN + 1023) / 1024;   // 49
    for (int ch = 0; ch < NCHUNK; ++ch) {
        int i = ch * 1024 + tid;
        int v = (i < NN) ? g_deg[i] : 0;
        int x = v;
#pragma unroll
        for (int o = 1; o < 32; o <<= 1) {
            int t = __shfl_up_sync(0xffffffffu, x, o);
            if (lane >= o) x += t;
        }
        if (lane == 31) warpsums[wid] = x;
        __syncthreads();
        if (wid == 0) {
            int w = warpsums[lane];
#pragma unroll
            for (int o = 1; o < 32; o <<= 1) {
                int t = __shfl_up_sync(0xffffffffu, w, o);
                if (lane >= o) w += t;
            }
            warpsums[lane] = w;
        }
        __syncthreads();
        int incl = x + (wid > 0 ? warpsums[wid - 1] : 0);
        if (i < NN) g_off[i] = run + incl - v;
        run += warpsums[31];
        __syncthreads();
    }
}

__global__ void fill_adj_kernel(const int* __restrict__ ei) {
    int e = blockIdx.x * blockDim.x + threadIdx.x;   // exact grid
    int dst = ei[EE + e];
    int pos = atomicAdd(&g_cursor[dst], 1);
    g_adj[g_off[dst] + pos] = ei[e];
}

__global__ void cleanup_kernel() {
    int i = blockIdx.x * blockDim.x + threadIdx.x;
    if (i < NN) { g_deg[i] = 0; g_cursor[i] = 0; }
}

// ---------------------------------------------------------------------------
// Weight pre-split: hi = bf16(w), lo = bf16(w - float(hi)), plain [k][n]
// ---------------------------------------------------------------------------
__global__ void prep_w_kernel(const float* __restrict__ W1s,
                              const float* __restrict__ W2s) {
    int idx = blockIdx.x * 256 + threadIdx.x;   // 640*256 = 163840 exact
    int l = idx / 32768;
    int rem = idx & 32767;
    int mat = rem >> 14;
    int e = rem & 16383;
    const float* W = mat ? W2s : W1s;
    float w = W[(size_t)l * 16384 + e];
    __nv_bfloat16 hi = __float2bfloat16(w);
    float lo = w - __bfloat162float(hi);
    g_wh[mat][l][e] = hi;
    g_wl[mat][l][e] = __float2bfloat16(lo);
}

// ---------------------------------------------------------------------------
// Gather: z = h + sum_{j in adj(node)} h[j]   (launch index 3 -> ncu target)
// ---------------------------------------------------------------------------
__global__ __launch_bounds__(256) void gather_kernel(const float* __restrict__ x,
                                                     int insel) {
    const float* cur = (insel < 0) ? x : g_h[insel];
    int t = blockIdx.x * 256 + threadIdx.x;
    int node = t >> 5;
    int lane = t & 31;
    int off = 0, deg = 0;
    if (lane == 0) { off = g_off[node]; deg = g_deg[node]; }
    off = __shfl_sync(0xffffffffu, off, 0);
    deg = __shfl_sync(0xffffffffu, deg, 0);
    float4 acc = reinterpret_cast<const float4*>(cur + (size_t)node * DD)[lane];
    for (int j0 = 0; j0 < deg; j0 += 32) {
        int myidx = 0;
        if (j0 + lane < deg) myidx = g_adj[off + j0 + lane];
        int cnt = min(32, deg - j0);
        int tt = 0;
        for (; tt + 4 <= cnt; tt += 4) {
            int s0 = __shfl_sync(0xffffffffu, myidx, tt);
            int s1 = __shfl_sync(0xffffffffu, myidx, tt + 1);
            int s2 = __shfl_sync(0xffffffffu, myidx, tt + 2);
            int s3 = __shfl_sync(0xffffffffu, myidx, tt + 3);
            float4 v0 = reinterpret_cast<const float4*>(cur + (size_t)s0 * DD)[lane];
            float4 v1 = reinterpret_cast<const float4*>(cur + (size_t)s1 * DD)[lane];
            float4 v2 = reinterpret_cast<const float4*>(cur + (size_t)s2 * DD)[lane];
            float4 v3 = reinterpret_cast<const float4*>(cur + (size_t)s3 * DD)[lane];
            acc.x += v0.x; acc.y += v0.y; acc.z += v0.z; acc.w += v0.w;
            acc.x += v1.x; acc.y += v1.y; acc.z += v1.z; acc.w += v1.w;
            acc.x += v2.x; acc.y += v2.y; acc.z += v2.z; acc.w += v2.w;
            acc.x += v3.x; acc.y += v3.y; acc.z += v3.z; acc.w += v3.w;
        }
        for (; tt < cnt; ++tt) {
            int s0 = __shfl_sync(0xffffffffu, myidx, tt);
            float4 v0 = reinterpret_cast<const float4*>(cur + (size_t)s0 * DD)[lane];
            acc.x += v0.x; acc.y += v0.y; acc.z += v0.z; acc.w += v0.w;
        }
    }
    reinterpret_cast<float4*>(g_z + (size_t)node * DD)[lane] = acc;
}

// ---------------------------------------------------------------------------
// wmma bf16 3-split fused 2-layer MLP.
// 128 rows/CTA, 256 threads = 8 warps tiled 4(row) x 2(col):
//   warp w: wr = w>>1 -> rows wr*32..+31,  wc = w&1 -> cols wc*64..+63
// All four weight images (W1,W2 hi/lo) resident in smem for the whole kernel.
// ---------------------------------------------------------------------------
#define LDA 136
#define A_HI_OFF 0
#define A_LO_OFF 34816
#define B_OFF(m, p) (69632 + (m) * 69632 + (p) * 34816)
#define STG_OFF  208896
#define BIAS_OFF 221184
#define MLP_SMEM (BIAS_OFF + 256 * 4)   // 222208 bytes

__device__ __forceinline__ void copy_w_to_smem(__nv_bfloat16* dst,
                                               const __nv_bfloat16* src,
                                               int tid) {
#pragma unroll
    for (int it = 0; it < 8; ++it) {
        int idx = it * 256 + tid;       // 2048 uint4 total
        int k = idx >> 4;
        int q = idx & 15;
        *reinterpret_cast<uint4*>(
            reinterpret_cast<char*>(dst) + (size_t)k * (LDA * 2) + q * 16) =
            reinterpret_cast<const uint4*>(src + (size_t)k * DD)[q];
    }
}

__global__ __launch_bounds__(256) void mlp_wmma_kernel(
    int l, int outsel,
    const float* __restrict__ b1s, const float* __restrict__ b2s) {
    extern __shared__ char sm[];
    __nv_bfloat16* Ah = reinterpret_cast<__nv_bfloat16*>(sm + A_HI_OFF);
    __nv_bfloat16* Al = reinterpret_cast<__nv_bfloat16*>(sm + A_LO_OFF);
    float* bias = reinterpret_cast<float*>(sm + BIAS_OFF);

    const int tid = threadIdx.x;
    const int wid = tid >> 5;
    const int lane = tid & 31;
    const int wr = wid >> 1;          // 0..3
    const int wc = wid & 1;           // 0..1
    const int row0 = blockIdx.x * 128;
    float* stage = reinterpret_cast<float*>(sm + STG_OFF) + wid * 16 * 24;

    // biases
    if (tid < 128) bias[tid] = b1s[(size_t)l * DD + tid];
    else bias[tid] = b2s[(size_t)l * DD + (tid - 128)];

    // all weight images upfront
    copy_w_to_smem(reinterpret_cast<__nv_bfloat16*>(sm + B_OFF(0, 0)), g_wh[0][l], tid);
    copy_w_to_smem(reinterpret_cast<__nv_bfloat16*>(sm + B_OFF(0, 1)), g_wl[0][l], tid);
    copy_w_to_smem(reinterpret_cast<__nv_bfloat16*>(sm + B_OFF(1, 0)), g_wh[1][l], tid);
    copy_w_to_smem(reinterpret_cast<__nv_bfloat16*>(sm + B_OFF(1, 1)), g_wl[1][l], tid);

    // z rows -> split into Ah/Al
#pragma unroll
    for (int it = 0; it < 16; ++it) {
        int i = it * 256 + tid;          // 4096 float4s
        int r = i >> 5, c4 = i & 31;
        int grow = row0 + r;
        float4 v = make_float4(0.f, 0.f, 0.f, 0.f);
        if (grow < NN)
            v = *reinterpret_cast<const float4*>(g_z + (size_t)grow * DD + c4 * 4);
        __nv_bfloat16 hx = __float2bfloat16(v.x), hy = __float2bfloat16(v.y);
        __nv_bfloat16 hz = __float2bfloat16(v.z), hw = __float2bfloat16(v.w);
        __nv_bfloat162 ph0(hx, hy), ph1(hz, hw);
        __nv_bfloat162 pl0(__float2bfloat16(v.x - __bfloat162float(hx)),
                           __float2bfloat16(v.y - __bfloat162float(hy)));
        __nv_bfloat162 pl1(__float2bfloat16(v.z - __bfloat162float(hz)),
                           __float2bfloat16(v.w - __bfloat162float(hw)));
        uint2 hi, lo;
        hi.x = *reinterpret_cast<uint32_t*>(&ph0);
        hi.y = *reinterpret_cast<uint32_t*>(&ph1);
        lo.x = *reinterpret_cast<uint32_t*>(&pl0);
        lo.y = *reinterpret_cast<uint32_t*>(&pl1);
        size_t boff = (size_t)r * (LDA * 2) + c4 * 8;
        *reinterpret_cast<uint2*>(reinterpret_cast<char*>(Ah) + boff) = hi;
        *reinterpret_cast<uint2*>(reinterpret_cast<char*>(Al) + boff) = lo;
    }
    __syncthreads();

    wmma::fragment<wmma::matrix_a, 16, 16, 16, __nv_bfloat16, wmma::row_major> af[2];
    wmma::fragment<wmma::matrix_b, 16, 16, 16, __nv_bfloat16, wmma::row_major> bf[4];
    wmma::fragment<wmma::accumulator, 16, 16, 16, float> cf[2][4];

    // ================= GEMM1 =================
#pragma unroll
    for (int i = 0; i < 2; ++i)
#pragma unroll
        for (int j = 0; j < 4; ++j) wmma::fill_fragment(cf[i][j], 0.f);
    {
        const __nv_bfloat16* Bh = reinterpret_cast<__nv_bfloat16*>(sm + B_OFF(0, 0));
        const __nv_bfloat16* Bl = reinterpret_cast<__nv_bfloat16*>(sm + B_OFF(0, 1));
        const __nv_bfloat16* Ab[3] = {Ah, Ah, Al};
        const __nv_bfloat16* Bb[3] = {Bh, Bl, Bh};
#pragma unroll
        for (int p = 0; p < 3; ++p)
#pragma unroll
            for (int k = 0; k < 8; ++k) {
#pragma unroll
                for (int i = 0; i < 2; ++i)
                    wmma::load_matrix_sync(af[i],
                        Ab[p] + (wr * 32 + i * 16) * LDA + k * 16, LDA);
#pragma unroll
                for (int j = 0; j < 4; ++j)
                    wmma::load_matrix_sync(bf[j],
                        Bb[p] + (k * 16) * LDA + wc * 64 + j * 16, LDA);
#pragma unroll
                for (int i = 0; i < 2; ++i)
#pragma unroll
                    for (int j = 0; j < 4; ++j)
                        wmma::mma_sync(cf[i][j], af[i], bf[j], cf[i][j]);
            }
    }
    __syncthreads();   // all warps done reading A before epilogue overwrites it

    // epilogue1: t = relu(D1 + b1) -> re-split into Ah/Al (rows wr*32.., cols wc*64..)
#pragma unroll
    for (int i = 0; i < 2; ++i)
#pragma unroll
        for (int j = 0; j < 4; ++j) {
            wmma::store_matrix_sync(stage, cf[i][j], 24, wmma::mem_row_major);
            __syncwarp();
            int r = lane >> 1;
            int cb = (lane & 1) * 8;
#pragma unroll
            for (int e = 0; e < 8; ++e) {
                int c = cb + e;
                int gc = wc * 64 + j * 16 + c;
                float t = fmaxf(stage[r * 24 + c] + bias[gc], 0.f);
                __nv_bfloat16 hi = __float2bfloat16(t);
                int pos = (wr * 32 + i * 16 + r) * LDA + gc;
                Ah[pos] = hi;
                Al[pos] = __float2bfloat16(t - __bfloat162float(hi));
            }
            __syncwarp();
        }
    __syncthreads();

    // ================= GEMM2 =================
#pragma unroll
    for (int i = 0; i < 2; ++i)
#pragma unroll
        for (int j = 0; j < 4; ++j) wmma::fill_fragment(cf[i][j], 0.f);
    {
        const __nv_bfloat16* Bh = reinterpret_cast<__nv_bfloat16*>(sm + B_OFF(1, 0));
        const __nv_bfloat16* Bl = reinterpret_cast<__nv_bfloat16*>(sm + B_OFF(1, 1));
        const __nv_bfloat16* Ab[3] = {Ah, Ah, Al};
        const __nv_bfloat16* Bb[3] = {Bh, Bl, Bh};
#pragma unroll
        for (int p = 0; p < 3; ++p)
#pragma unroll
            for (int k = 0; k < 8; ++k) {
#pragma unroll
                for (int i = 0; i < 2; ++i)
                    wmma::load_matrix_sync(af[i],
                        Ab[p] + (wr * 32 + i * 16) * LDA + k * 16, LDA);
#pragma unroll
                for (int j = 0; j < 4; ++j)
                    wmma::load_matrix_sync(bf[j],
                        Bb[p] + (k * 16) * LDA + wc * 64 + j * 16, LDA);
#pragma unroll
                for (int i = 0; i < 2; ++i)
#pragma unroll
                    for (int j = 0; j < 4; ++j)
                        wmma::mma_sync(cf[i][j], af[i], bf[j], cf[i][j]);
            }
    }
    // epilogue2: h = relu(D2 + b2) -> global
    float* hout = g_h[outsel];
#pragma unroll
    for (int i = 0; i < 2; ++i)
#pragma unroll
        for (int j = 0; j < 4; ++j) {
            wmma::store_matrix_sync(stage, cf[i][j], 24, wmma::mem_row_major);
            __syncwarp();
            int r = lane >> 1;
            int cb = (lane & 1) * 8;
            int grow = row0 + wr * 32 + i * 16 + r;
            if (grow < NN) {
                int gc = wc * 64 + j * 16 + cb;
                const float* bb = bias + 128 + gc;
                const float* ss = stage + r * 24 + cb;
                float4 o0, o1;
                o0.x = fmaxf(ss[0] + bb[0], 0.f);
                o0.y = fmaxf(ss[1] + bb[1], 0.f);
                o0.z = fmaxf(ss[2] + bb[2], 0.f);
                o0.w = fmaxf(ss[3] + bb[3], 0.f);
                o1.x = fmaxf(ss[4] + bb[4], 0.f);
                o1.y = fmaxf(ss[5] + bb[5], 0.f);
                o1.z = fmaxf(ss[6] + bb[6], 0.f);
                o1.w = fmaxf(ss[7] + bb[7], 0.f);
                float* dst = hout + (size_t)grow * DD + gc;
                *reinterpret_cast<float4*>(dst) = o0;
                *reinterpret_cast<float4*>(dst + 4) = o1;
            }
            __syncwarp();
        }
}

// ---------------------------------------------------------------------------
// Pooling + head
// ---------------------------------------------------------------------------
__global__ void poolzero_kernel() {
    int i = blockIdx.x * blockDim.x + threadIdx.x;   // 500*256 exact
    g_sums[i] = 0.f;
    if (i < GG) g_cnt[i] = 0.f;
}
__global__ void pool_kernel(const int* __restrict__ batch) {
    const float* cur = g_h[(LL - 1) & 1];
    int t = blockIdx.x * 256 + threadIdx.x;
    int n = t >> 5;
    int lane = t & 31;
    int b = 0;
    if (lane == 0) b = batch[n];
    b = __shfl_sync(0xffffffffu, b, 0);
    float4 v = reinterpret_cast<const float4*>(cur + (size_t)n * DD)[lane];
    float* p = g_sums + (size_t)b * DD + lane * 4;
    asm volatile("red.global.add.v4.f32 [%0], {%1,%2,%3,%4};"
                 :: "l"(p), "f"(v.x), "f"(v.y), "f"(v.z), "f"(v.w) : "memory");
    if (lane == 0) atomicAdd(&g_cnt[b], 1.0f);
}
__global__ void head_kernel(const float* __restrict__ Wh,
                            const float* __restrict__ bh,
                            float* __restrict__ out) {
    int g = blockIdx.x;
    int d = threadIdx.x;
    float c = fmaxf(g_cnt[g], 1.0f);
    float v = g_sums[(size_t)g * DD + d] / c * Wh[d];
#pragma unroll
    for (int o = 16; o > 0; o >>= 1)
        v += __shfl_down_sync(0xffffffffu, v, o);
    __shared__ float red[4];
    if ((d & 31) == 0) red[d >> 5] = v;
    __syncthreads();
    if (d == 0) out[g] = red[0] + red[1] + red[2] + red[3] + bh[0];
}

// ---------------------------------------------------------------------------
extern "C" void kernel_launch(void* const* d_in, const int* in_sizes, int n_in,
                              void* d_out, int out_size) {
    const float* x    = (const float*)d_in[0];
    const int*   ei   = (const int*)  d_in[1];
    const int*   batch= (const int*)  d_in[2];
    const float* W1s  = (const float*)d_in[3];
    const float* b1s  = (const float*)d_in[4];
    const float* W2s  = (const float*)d_in[5];
    const float* b2s  = (const float*)d_in[6];
    const float* Wh   = (const float*)d_in[7];
    const float* bh   = (const float*)d_in[8];
    float* out = (float*)d_out;

    static bool attr_done = false;
    if (!attr_done) {
        cudaFuncSetAttribute(mlp_wmma_kernel,
                             cudaFuncAttributeMaxDynamicSharedMemorySize,
                             MLP_SMEM);
        attr_done = true;
    }

    // CSR build (g_deg/g_cursor are zero on entry; restored by cleanup_kernel)
    deg_count_kernel<<<EE / 256, 256>>>(ei);           // launch 0
    scan_all_kernel<<<1, 1024>>>();                    // launch 1
    fill_adj_kernel<<<EE / 256, 256>>>(ei);            // launch 2

    gather_kernel<<<NN * 32 / 256, 256>>>(x, -1);      // launch 3 (ncu target)
    prep_w_kernel<<<640, 256>>>(W1s, W2s);             // launch 4
    mlp_wmma_kernel<<<(NN + 127) / 128, 256, MLP_SMEM>>>(0, 0, b1s, b2s);

    int insel = 0;
    for (int l = 1; l < LL; ++l) {
        gather_kernel<<<NN * 32 / 256, 256>>>(x, insel);
        mlp_wmma_kernel<<<(NN + 127) / 128, 256, MLP_SMEM>>>(l, l & 1, b1s, b2s);
        insel = l & 1;
    }
    poolzero_kernel<<<500, 256>>>();
    pool_kernel<<<NN * 32 / 256, 256>>>(batch);
    head_kernel<<<GG, 128>>>(Wh, bh, out);
    cleanup_kernel<<<(NN + 255) / 256, 256>>>();
}

// round 9
// speedup vs baseline: 2.3357x; 1.3322x over previous
#include <cuda_runtime.h>
#include <cuda_bf16.h>
#include <cstdint>

#define NN 50000
#define EE 800000
#define DD 128
#define LL 5
#define GG 1000

#define SCAN_B 512
#define NB ((NN + SCAN_B - 1) / SCAN_B)   // 98

// ---------------------------------------------------------------------------
// Device global scratch (no allocation allowed)
// ---------------------------------------------------------------------------
__device__ float g_z[NN * DD];
__device__ float g_h[2][NN * DD];
__device__ float g_sums[GG * DD];
__device__ float g_cnt[GG];
__device__ int g_deg[NN];      // zero on entry; cleanup_kernel restores
__device__ int g_off[NN];
__device__ int g_cursor[NN];   // zero on entry; cleanup_kernel restores
__device__ int g_adj[EE];
__device__ int g_scan[NB * SCAN_B];
__device__ int g_bsums[NB];
__device__ int g_boff[NB];
// Pre-split weight images [mat(0=W1,1=W2)][layer][k*128+n]
__device__ __nv_bfloat16 g_wh[2][LL][DD * DD];
__device__ __nv_bfloat16 g_wl[2][LL][DD * DD];

// ---------------------------------------------------------------------------
// CSR build
// ---------------------------------------------------------------------------
__global__ void deg_count_kernel(const int* __restrict__ ei) {
    int e = blockIdx.x * blockDim.x + threadIdx.x;   // exact grid EE/256
    atomicAdd(&g_deg[ei[EE + e]], 1);
}
__global__ void scan_blocks_kernel() {
    __shared__ int s[SCAN_B];
    int tid = threadIdx.x;
    int i = blockIdx.x * SCAN_B + tid;
    int v = (i < NN) ? g_deg[i] : 0;
    s[tid] = v;
    __syncthreads();
#pragma unroll
    for (int o = 1; o < SCAN_B; o <<= 1) {
        int t = 0;
        if (tid >= o) t = s[tid - o];
        __syncthreads();
        s[tid] += t;
        __syncthreads();
    }
    g_scan[i] = s[tid];
    if (tid == SCAN_B - 1) g_bsums[blockIdx.x] = s[tid];
}
__global__ void scan_top_kernel() {
    __shared__ int s[128];
    int tid = threadIdx.x;
    int v = (tid < NB) ? g_bsums[tid] : 0;
    s[tid] = v;
    __syncthreads();
#pragma unroll
    for (int o = 1; o < 128; o <<= 1) {
        int t = 0;
        if (tid >= o) t = s[tid - o];
        __syncthreads();
        s[tid] += t;
        __syncthreads();
    }
    if (tid < NB) g_boff[tid] = s[tid] - v;
}
__global__ void fill_off_kernel() {
    int i = blockIdx.x * blockDim.x + threadIdx.x;
    if (i < NN) g_off[i] = g_scan[i] - g_deg[i] + g_boff[i / SCAN_B];
}
__global__ void fill_adj_kernel(const int* __restrict__ ei) {
    int e = blockIdx.x * blockDim.x + threadIdx.x;
    int dst = ei[EE + e];
    int pos = atomicAdd(&g_cursor[dst], 1);
    g_adj[g_off[dst] + pos] = ei[e];
}
__global__ void cleanup_kernel() {
    int i = blockIdx.x * blockDim.x + threadIdx.x;
    if (i < NN) { g_deg[i] = 0; g_cursor[i] = 0; }
}

// ---------------------------------------------------------------------------
// Weight pre-split
// ---------------------------------------------------------------------------
__global__ void prep_w_kernel(const float* __restrict__ W1s,
                              const float* __restrict__ W2s) {
    int idx = blockIdx.x * 256 + threadIdx.x;   // 640*256 = 163840 exact
    int l = idx / 32768;
    int rem = idx & 32767;
    int mat = rem >> 14;
    int e = rem & 16383;
    const float* W = mat ? W2s : W1s;
    float w = W[(size_t)l * 16384 + e];
    __nv_bfloat16 hi = __float2bfloat16(w);
    float lo = w - __bfloat162float(hi);
    g_wh[mat][l][e] = hi;
    g_wl[mat][l][e] = __float2bfloat16(lo);
}

// ---------------------------------------------------------------------------
// Gather: z = h + sum_{j in adj(node)} h[j]   (at LTS roofline; unchanged)
// ---------------------------------------------------------------------------
__global__ __launch_bounds__(256) void gather_kernel(const float* __restrict__ x,
                                                     int insel) {
    const float* cur = (insel < 0) ? x : g_h[insel];
    int t = blockIdx.x * 256 + threadIdx.x;
    int node = t >> 5;
    int lane = t & 31;
    int off = 0, deg = 0;
    if (lane == 0) { off = g_off[node]; deg = g_deg[node]; }
    off = __shfl_sync(0xffffffffu, off, 0);
    deg = __shfl_sync(0xffffffffu, deg, 0);
    float4 acc = reinterpret_cast<const float4*>(cur + (size_t)node * DD)[lane];
    for (int j0 = 0; j0 < deg; j0 += 32) {
        int myidx = 0;
        if (j0 + lane < deg) myidx = g_adj[off + j0 + lane];
        int cnt = min(32, deg - j0);
        int tt = 0;
        for (; tt + 4 <= cnt; tt += 4) {
            int s0 = __shfl_sync(0xffffffffu, myidx, tt);
            int s1 = __shfl_sync(0xffffffffu, myidx, tt + 1);
            int s2 = __shfl_sync(0xffffffffu, myidx, tt + 2);
            int s3 = __shfl_sync(0xffffffffu, myidx, tt + 3);
            float4 v0 = reinterpret_cast<const float4*>(cur + (size_t)s0 * DD)[lane];
            float4 v1 = reinterpret_cast<const float4*>(cur + (size_t)s1 * DD)[lane];
            float4 v2 = reinterpret_cast<const float4*>(cur + (size_t)s2 * DD)[lane];
            float4 v3 = reinterpret_cast<const float4*>(cur + (size_t)s3 * DD)[lane];
            acc.x += v0.x; acc.y += v0.y; acc.z += v0.z; acc.w += v0.w;
            acc.x += v1.x; acc.y += v1.y; acc.z += v1.z; acc.w += v1.w;
            acc.x += v2.x; acc.y += v2.y; acc.z += v2.z; acc.w += v2.w;
            acc.x += v3.x; acc.y += v3.y; acc.z += v3.z; acc.w += v3.w;
        }
        for (; tt < cnt; ++tt) {
            int s0 = __shfl_sync(0xffffffffu, myidx, tt);
            float4 v0 = reinterpret_cast<const float4*>(cur + (size_t)s0 * DD)[lane];
            acc.x += v0.x; acc.y += v0.y; acc.z += v0.z; acc.w += v0.w;
        }
    }
    reinterpret_cast<float4*>(g_z + (size_t)node * DD)[lane] = acc;
}

// ---------------------------------------------------------------------------
// Raw mma.sync bf16 3-split fused 2-layer MLP.
// 128 rows/CTA, 256 threads = 8 warps tiled 4(row) x 2(col).
// Register-resident epilogues (no smem staging of accumulators).
// ---------------------------------------------------------------------------
#define LDA 136
#define A_HI_OFF 0
#define A_LO_OFF 34816
#define B_OFF(m, p) (69632 + (m) * 69632 + (p) * 34816)
#define BIAS_OFF 208896
#define MLP_SMEM (BIAS_OFF + 256 * 4)   // 209920 bytes

__device__ __forceinline__ uint32_t smem_u32(const void* p) {
    uint32_t a;
    asm("{ .reg .u64 t; cvta.to.shared.u64 t, %1; cvt.u32.u64 %0, t; }"
        : "=r"(a) : "l"(p));
    return a;
}
__device__ __forceinline__ void ldsm_x4(uint32_t* r, uint32_t addr) {
    asm volatile("ldmatrix.sync.aligned.m8n8.x4.shared.b16 {%0,%1,%2,%3}, [%4];"
                 : "=r"(r[0]), "=r"(r[1]), "=r"(r[2]), "=r"(r[3]) : "r"(addr));
}
__device__ __forceinline__ void ldsm_x4t(uint32_t* r, uint32_t addr) {
    asm volatile("ldmatrix.sync.aligned.m8n8.x4.trans.shared.b16 {%0,%1,%2,%3}, [%4];"
                 : "=r"(r[0]), "=r"(r[1]), "=r"(r[2]), "=r"(r[3]) : "r"(addr));
}
__device__ __forceinline__ void mma16816(float* c, const uint32_t* a,
                                         const uint32_t* b) {
    asm volatile("mma.sync.aligned.m16n8k16.row.col.f32.bf16.bf16.f32 "
                 "{%0,%1,%2,%3}, {%4,%5,%6,%7}, {%8,%9}, {%0,%1,%2,%3};"
                 : "+f"(c[0]), "+f"(c[1]), "+f"(c[2]), "+f"(c[3])
                 : "r"(a[0]), "r"(a[1]), "r"(a[2]), "r"(a[3]),
                   "r"(b[0]), "r"(b[1]));
}
__device__ __forceinline__ void copy_w_to_smem(char* dst,
                                               const __nv_bfloat16* src,
                                               int tid) {
#pragma unroll
    for (int it = 0; it < 8; ++it) {
        int idx = it * 256 + tid;       // 2048 uint4 total
        int k = idx >> 4;
        int q = idx & 15;
        *reinterpret_cast<uint4*>(dst + (size_t)k * (LDA * 2) + q * 16) =
            reinterpret_cast<const uint4*>(src + (size_t)k * DD)[q];
    }
}

__global__ __launch_bounds__(256) void mlp_mma_kernel(
    int l, int outsel,
    const float* __restrict__ b1s, const float* __restrict__ b2s) {
    extern __shared__ char sm[];
    float* bias = reinterpret_cast<float*>(sm + BIAS_OFF);

    const int tid = threadIdx.x;
    const int wid = tid >> 5;
    const int lane = tid & 31;
    const int wr = wid >> 1;          // 0..3 row tile
    const int wc = wid & 1;           // 0..1 col tile
    const int row0 = blockIdx.x * 128;

    const uint32_t ah_b = smem_u32(sm + A_HI_OFF);
    const uint32_t al_b = smem_u32(sm + A_LO_OFF);
    const uint32_t b1h = smem_u32(sm + B_OFF(0, 0));
    const uint32_t b1l = smem_u32(sm + B_OFF(0, 1));
    const uint32_t b2h = smem_u32(sm + B_OFF(1, 0));
    const uint32_t b2l = smem_u32(sm + B_OFF(1, 1));

    if (tid < 128) bias[tid] = b1s[(size_t)l * DD + tid];
    else bias[tid] = b2s[(size_t)l * DD + (tid - 128)];

    copy_w_to_smem(sm + B_OFF(0, 0), g_wh[0][l], tid);
    copy_w_to_smem(sm + B_OFF(0, 1), g_wl[0][l], tid);
    copy_w_to_smem(sm + B_OFF(1, 0), g_wh[1][l], tid);
    copy_w_to_smem(sm + B_OFF(1, 1), g_wl[1][l], tid);

    // z rows -> split into Ah/Al
#pragma unroll
    for (int it = 0; it < 16; ++it) {
        int i = it * 256 + tid;
        int r = i >> 5, c4 = i & 31;
        int grow = row0 + r;
        float4 v = make_float4(0.f, 0.f, 0.f, 0.f);
        if (grow < NN)
            v = *reinterpret_cast<const float4*>(g_z + (size_t)grow * DD + c4 * 4);
        __nv_bfloat16 hx = __float2bfloat16(v.x), hy = __float2bfloat16(v.y);
        __nv_bfloat16 hz = __float2bfloat16(v.z), hw = __float2bfloat16(v.w);
        __nv_bfloat162 ph0(hx, hy), ph1(hz, hw);
        __nv_bfloat162 pl0(__float2bfloat16(v.x - __bfloat162float(hx)),
                           __float2bfloat16(v.y - __bfloat162float(hy)));
        __nv_bfloat162 pl1(__float2bfloat16(v.z - __bfloat162float(hz)),
                           __float2bfloat16(v.w - __bfloat162float(hw)));
        uint2 hi, lo;
        hi.x = *reinterpret_cast<uint32_t*>(&ph0);
        hi.y = *reinterpret_cast<uint32_t*>(&ph1);
        lo.x = *reinterpret_cast<uint32_t*>(&pl0);
        lo.y = *reinterpret_cast<uint32_t*>(&pl1);
        size_t boff = (size_t)r * (LDA * 2) + c4 * 8;
        *reinterpret_cast<uint2*>(sm + A_HI_OFF + boff) = hi;
        *reinterpret_cast<uint2*>(sm + A_LO_OFF + boff) = lo;
    }
    __syncthreads();

    // per-lane ldmatrix address components
    const int a_row = lane & 15;                 // row within 16
    const int a_koff = (lane >> 4) * 8;          // k offset 0/8
    const int b_krow = (lane & 7) + ((lane >> 3) & 1) * 8;
    const int b_noff = (lane >> 4) * 8;

    float cf[2][8][4];
    const int eg = lane >> 2;          // epilogue row-in-8
    const int et = 2 * (lane & 3);     // epilogue col pair base

    // ================= GEMM1 =================
#pragma unroll
    for (int i = 0; i < 2; ++i)
#pragma unroll
        for (int j = 0; j < 8; ++j)
#pragma unroll
            for (int q = 0; q < 4; ++q) cf[i][j][q] = 0.f;
    {
        const uint32_t Ab[3] = {ah_b, ah_b, al_b};
        const uint32_t Bb[3] = {b1h, b1l, b1h};
#pragma unroll
        for (int p = 0; p < 3; ++p)
#pragma unroll
            for (int k = 0; k < 8; ++k) {
                uint32_t a[2][4];
#pragma unroll
                for (int i = 0; i < 2; ++i)
                    ldsm_x4(a[i], Ab[p] +
                        ((wr * 32 + i * 16 + a_row) * LDA + k * 16 + a_koff) * 2);
                uint32_t b[8][2];
#pragma unroll
                for (int q = 0; q < 4; ++q) {
                    uint32_t r4[4];
                    ldsm_x4t(r4, Bb[p] +
                        ((k * 16 + b_krow) * LDA + wc * 64 + q * 16 + b_noff) * 2);
                    b[2 * q][0] = r4[0]; b[2 * q][1] = r4[1];
                    b[2 * q + 1][0] = r4[2]; b[2 * q + 1][1] = r4[3];
                }
#pragma unroll
                for (int i = 0; i < 2; ++i)
#pragma unroll
                    for (int j = 0; j < 8; ++j)
                        mma16816(cf[i][j], a[i], b[j]);
            }
    }
    __syncthreads();   // everyone done reading A before overwrite

    // epilogue1 (registers): t = relu(D1 + b1) -> split back into Ah/Al
#pragma unroll
    for (int i = 0; i < 2; ++i)
#pragma unroll
        for (int j = 0; j < 8; ++j) {
            int gc = wc * 64 + j * 8 + et;
            float ba = bias[gc], bb = bias[gc + 1];
#pragma unroll
            for (int h = 0; h < 2; ++h) {
                int row = wr * 32 + i * 16 + eg + h * 8;
                float t0 = fmaxf(cf[i][j][2 * h] + ba, 0.f);
                float t1 = fmaxf(cf[i][j][2 * h + 1] + bb, 0.f);
                __nv_bfloat16 h0 = __float2bfloat16(t0), h1 = __float2bfloat16(t1);
                __nv_bfloat162 ph(h0, h1);
                __nv_bfloat162 pl(__float2bfloat16(t0 - __bfloat162float(h0)),
                                  __float2bfloat16(t1 - __bfloat162float(h1)));
                size_t boff = (size_t)row * (LDA * 2) + gc * 2;
                *reinterpret_cast<uint32_t*>(sm + A_HI_OFF + boff) =
                    *reinterpret_cast<uint32_t*>(&ph);
                *reinterpret_cast<uint32_t*>(sm + A_LO_OFF + boff) =
                    *reinterpret_cast<uint32_t*>(&pl);
            }
        }
    __syncthreads();

    // ================= GEMM2 =================
#pragma unroll
    for (int i = 0; i < 2; ++i)
#pragma unroll
        for (int j = 0; j < 8; ++j)
#pragma unroll
            for (int q = 0; q < 4; ++q) cf[i][j][q] = 0.f;
    {
        const uint32_t Ab[3] = {ah_b, ah_b, al_b};
        const uint32_t Bb[3] = {b2h, b2l, b2h};
#pragma unroll
        for (int p = 0; p < 3; ++p)
#pragma unroll
            for (int k = 0; k < 8; ++k) {
                uint32_t a[2][4];
#pragma unroll
                for (int i = 0; i < 2; ++i)
                    ldsm_x4(a[i], Ab[p] +
                        ((wr * 32 + i * 16 + a_row) * LDA + k * 16 + a_koff) * 2);
                uint32_t b[8][2];
#pragma unroll
                for (int q = 0; q < 4; ++q) {
                    uint32_t r4[4];
                    ldsm_x4t(r4, Bb[p] +
                        ((k * 16 + b_krow) * LDA + wc * 64 + q * 16 + b_noff) * 2);
                    b[2 * q][0] = r4[0]; b[2 * q][1] = r4[1];
                    b[2 * q + 1][0] = r4[2]; b[2 * q + 1][1] = r4[3];
                }
#pragma unroll
                for (int i = 0; i < 2; ++i)
#pragma unroll
                    for (int j = 0; j < 8; ++j)
                        mma16816(cf[i][j], a[i], b[j]);
            }
    }
    // epilogue2 (registers): h = relu(D2 + b2) -> global float2 stores
    float* hout = g_h[outsel];
#pragma unroll
    for (int i = 0; i < 2; ++i)
#pragma unroll
        for (int j = 0; j < 8; ++j) {
            int gc = wc * 64 + j * 8 + et;
            float ba = bias[128 + gc], bb = bias[128 + gc + 1];
#pragma unroll
            for (int h = 0; h < 2; ++h) {
                int grow = row0 + wr * 32 + i * 16 + eg + h * 8;
                if (grow < NN) {
                    float2 o;
                    o.x = fmaxf(cf[i][j][2 * h] + ba, 0.f);
                    o.y = fmaxf(cf[i][j][2 * h + 1] + bb, 0.f);
                    *reinterpret_cast<float2*>(hout + (size_t)grow * DD + gc) = o;
                }
            }
        }
}

// ---------------------------------------------------------------------------
// Pooling + head
// ---------------------------------------------------------------------------
__global__ void poolzero_kernel() {
    int i = blockIdx.x * blockDim.x + threadIdx.x;
    g_sums[i] = 0.f;
    if (i < GG) g_cnt[i] = 0.f;
}
__global__ void pool_kernel(const int* __restrict__ batch) {
    const float* cur = g_h[(LL - 1) & 1];
    int t = blockIdx.x * 256 + threadIdx.x;
    int n = t >> 5;
    int lane = t & 31;
    int b = 0;
    if (lane == 0) b = batch[n];
    b = __shfl_sync(0xffffffffu, b, 0);
    float4 v = reinterpret_cast<const float4*>(cur + (size_t)n * DD)[lane];
    float* p = g_sums + (size_t)b * DD + lane * 4;
    asm volatile("red.global.add.v4.f32 [%0], {%1,%2,%3,%4};"
                 :: "l"(p), "f"(v.x), "f"(v.y), "f"(v.z), "f"(v.w) : "memory");
    if (lane == 0) atomicAdd(&g_cnt[b], 1.0f);
}
__global__ void head_kernel(const float* __restrict__ Wh,
                            const float* __restrict__ bh,
                            float* __restrict__ out) {
    int g = blockIdx.x;
    int d = threadIdx.x;
    float c = fmaxf(g_cnt[g], 1.0f);
    float v = g_sums[(size_t)g * DD + d] / c * Wh[d];
#pragma unroll
    for (int o = 16; o > 0; o >>= 1)
        v += __shfl_down_sync(0xffffffffu, v, o);
    __shared__ float red[4];
    if ((d & 31) == 0) red[d >> 5] = v;
    __syncthreads();
    if (d == 0) out[g] = red[0] + red[1] + red[2] + red[3] + bh[0];
}

// ---------------------------------------------------------------------------
extern "C" void kernel_launch(void* const* d_in, const int* in_sizes, int n_in,
                              void* d_out, int out_size) {
    const float* x    = (const float*)d_in[0];
    const int*   ei   = (const int*)  d_in[1];
    const int*   batch= (const int*)  d_in[2];
    const float* W1s  = (const float*)d_in[3];
    const float* b1s  = (const float*)d_in[4];
    const float* W2s  = (const float*)d_in[5];
    const float* b2s  = (const float*)d_in[6];
    const float* Wh   = (const float*)d_in[7];
    const float* bh   = (const float*)d_in[8];
    float* out = (float*)d_out;

    static bool attr_done = false;
    if (!attr_done) {
        cudaFuncSetAttribute(mlp_mma_kernel,
                             cudaFuncAttributeMaxDynamicSharedMemorySize,
                             MLP_SMEM);
        attr_done = true;
    }

    prep_w_kernel<<<640, 256>>>(W1s, W2s);

    deg_count_kernel<<<EE / 256, 256>>>(ei);
    scan_blocks_kernel<<<NB, SCAN_B>>>();
    scan_top_kernel<<<1, 128>>>();
    fill_off_kernel<<<(NN + 255) / 256, 256>>>();
    fill_adj_kernel<<<EE / 256, 256>>>(ei);

    int insel = -1;
    for (int l = 0; l < LL; ++l) {
        gather_kernel<<<NN * 32 / 256, 256>>>(x, insel);
        mlp_mma_kernel<<<(NN + 127) / 128, 256, MLP_SMEM>>>(l, l & 1, b1s, b2s);
        insel = l & 1;
    }
    poolzero_kernel<<<500, 256>>>();
    pool_kernel<<<NN * 32 / 256, 256>>>(batch);
    head_kernel<<<GG, 128>>>(Wh, bh, out);
    cleanup_kernel<<<(NN + 255) / 256, 256>>>();
}